// round 6
// baseline (speedup 1.0000x reference)
#include <cuda_runtime.h>
#include <cuda_bf16.h>
#include <math.h>
#include <stdint.h>

// Problem constants
#define NB   8
#define TT   512
#define DD   512
#define HH   1024
#define NTOK 4096      // NB*TT
#define SS   2
#define GG   2
#define NGR  6
#define CC   32
#define KK   3
#define NEVT 50

// GEMM tiling
#define BM 128
#define BN 128
#define BK 16
#define MAXTILES 40

// ---------------- scratch (device globals; no cudaMalloc allowed) ----------
__device__ float g_h1s[NTOK * (SS * HH)];    // shared expert hidden   [4096,2048]
__device__ float g_outs[NTOK * (SS * DD)];   // shared expert out      [4096,1024]
__device__ float g_h1g[NTOK * (GG * HH)];    // group expert hidden (perm order)
__device__ float g_outg[NTOK * (GG * DD)];   // group expert out (token order)
__device__ int   g_gid[NTOK];
__device__ int   g_perm[NTOK];
__device__ int   g_tile_group[MAXTILES];
__device__ int   g_tile_m0[MAXTILES];
__device__ int   g_tile_end[MAXTILES];
__device__ int   g_ntiles;

// ---------------- prep: group ids + counting sort + tile table -------------
__global__ void k_prep(const int* __restrict__ nti, const int* __restrict__ e2g) {
    __shared__ int cnt[NGR];
    __shared__ int startS[NGR];
    __shared__ int cur[NGR];
    int t = threadIdx.x;
    if (t < NGR) cnt[t] = 0;
    __syncthreads();
    for (int n = t; n < NTOK; n += blockDim.x) {
        int v = nti[n];
        v = v < 0 ? 0 : (v > NEVT - 1 ? NEVT - 1 : v);
        int g = e2g[v];
        g_gid[n] = g;
        atomicAdd(&cnt[g], 1);
    }
    __syncthreads();
    if (t == 0) {
        int acc = 0, ntl = 0;
        for (int g = 0; g < NGR; g++) {
            startS[g] = acc;
            int c = cnt[g];
            for (int m0 = acc; m0 < acc + c; m0 += BM) {
                g_tile_group[ntl] = g;
                g_tile_m0[ntl]    = m0;
                g_tile_end[ntl]   = acc + c;
                ntl++;
            }
            acc += c;
        }
        g_ntiles = ntl;
        for (int g = 0; g < NGR; g++) cur[g] = startS[g];
    }
    __syncthreads();
    for (int n = t; n < NTOK; n += blockDim.x) {
        int g = g_gid[n];
        int pos = atomicAdd(&cur[g], 1);
        g_perm[pos] = n;
    }
}

// ---------------- PTX helpers ------------------------------------------------
__device__ __forceinline__ void split_tf32(float v, uint32_t& hi, uint32_t& lo) {
    asm("cvt.rna.tf32.f32 %0, %1;" : "=r"(hi) : "f"(v));
    float hif = __uint_as_float(hi);
    float rem = v - hif;
    asm("cvt.rna.tf32.f32 %0, %1;" : "=r"(lo) : "f"(rem));
}

#define MMA_TF32(d, a, b)                                                      \
    asm volatile("mma.sync.aligned.m16n8k8.row.col.f32.tf32.tf32.f32 "         \
                 "{%0,%1,%2,%3}, {%4,%5,%6,%7}, {%8,%9}, {%0,%1,%2,%3};"       \
                 : "+f"((d)[0]), "+f"((d)[1]), "+f"((d)[2]), "+f"((d)[3])      \
                 : "r"((a)[0]), "r"((a)[1]), "r"((a)[2]), "r"((a)[3]),         \
                   "r"((b)[0]), "r"((b)[1]))

__device__ __forceinline__ void cp16(void* smem_dst, const void* gsrc, bool pred) {
    uint32_t s = (uint32_t)__cvta_generic_to_shared(smem_dst);
    int sz = pred ? 16 : 0;
    asm volatile("cp.async.cg.shared.global [%0], [%1], 16, %2;"
                 :: "r"(s), "l"(gsrc), "r"(sz));
}
#define CP_COMMIT() asm volatile("cp.async.commit_group;")
#define CP_WAIT(N)  asm volatile("cp.async.wait_group %0;" :: "n"(N))

// ---------------- unified tf32 tensor-core GEMM ------------------------------
// MODE 0: h1s  = relu(x @ Ws1 + bs1)                     [4096,512]x[512,2048]
// MODE 1: outs = h1s @ Ws2 + bs2 (block-diag over s)     [4096,1024]x[1024,1024]
// MODE 2: h1g  = relu(gather(x) @ Wg1[g] + bg1[g])       grouped
// MODE 3: outg = h1g @ Wg2[g] + bg2[g], scatter          grouped
// 3xTF32 decomposition: D += Ahi*Bhi + Ahi*Blo + Alo*Bhi  (fp32 accum)
#define ASTRIDE 20    // (4*r + c) % 32 distinct -> conflict-free frag loads
#define BSTRIDE 132   // (4*k + n) % 32 -> <=2-way

template <int MODE>
__global__ void __launch_bounds__(256)
k_mma(const float* __restrict__ Aglob,
      const float* __restrict__ Bglob,
      const float* __restrict__ bias) {
    int m0, mend, g = 0;
    if (MODE == 2 || MODE == 3) {
        int tile = blockIdx.x;
        if (tile >= g_ntiles) return;
        g    = g_tile_group[tile];
        m0   = g_tile_m0[tile];
        mend = g_tile_end[tile];
    } else {
        m0   = blockIdx.x * BM;
        mend = NTOK;
    }
    const int colstart = blockIdx.y * BN;

    // column segment (expert index within the B bank)
    int seg, ldb;
    const float* Bp;
    int bias_off;
    if (MODE == 0) {            // cols = s*HH + h
        seg = colstart >> 10; int h0 = colstart & (HH - 1);
        Bp = Bglob + (size_t)seg * DD * HH + h0; ldb = HH;
        bias_off = colstart;
    } else if (MODE == 1) {     // cols = s*DD + d
        seg = colstart >> 9; int d0 = colstart & (DD - 1);
        Bp = Bglob + (size_t)seg * HH * DD + d0; ldb = DD;
        bias_off = colstart;
    } else if (MODE == 2) {     // cols = e*HH + h
        seg = colstart >> 10; int h0 = colstart & (HH - 1);
        Bp = Bglob + (size_t)(g * GG + seg) * DD * HH + h0; ldb = HH;
        bias_off = g * (GG * HH) + colstart;
    } else {                    // cols = e*DD + d
        seg = colstart >> 9; int d0 = colstart & (DD - 1);
        Bp = Bglob + (size_t)(g * GG + seg) * HH * DD + d0; ldb = DD;
        bias_off = g * (GG * DD) + colstart;
    }
    const int KTOT = (MODE == 0 || MODE == 2) ? DD : HH;

    __shared__ float As[2][BM][ASTRIDE];   // [buf][row][k]
    __shared__ float Bs[2][BK][BSTRIDE];   // [buf][k][n]

    const int tid  = threadIdx.x;
    const int lane = tid & 31;
    const int warp = tid >> 5;
    const int wm   = warp >> 2;      // 0..1  -> 64 rows
    const int wn   = warp & 3;       // 0..3  -> 32 cols

    // ---- loader mapping ----
    // A: row = tid>>1 (0..127), two float4 at colbase (tid&1)*8 + {0,4}
    // B: k   = tid>>4 (0..15),  two float4 at colbase (tid&15)*8 + {0,4}
    const int aRow = tid >> 1;
    const int aC   = (tid & 1) * 8;
    const int bK   = tid >> 4;
    const int bC   = (tid & 15) * 8;

    const float* Ap;
    bool aValid = true;
    {
        int p = m0 + aRow;
        if (MODE == 0) {
            Ap = Aglob + (size_t)p * DD;
        } else if (MODE == 1) {
            Ap = g_h1s + (size_t)p * (SS * HH) + seg * HH;
        } else if (MODE == 2) {
            aValid = p < mend;
            int tok = aValid ? g_perm[p] : 0;
            Ap = Aglob + (size_t)tok * DD;
        } else {
            aValid = p < mend;
            int pc = aValid ? p : 0;
            Ap = g_h1g + (size_t)pc * (GG * HH) + seg * HH;
        }
    }

    auto load_tiles = [&](int buf, int kk) {
        cp16(&As[buf][aRow][aC],     Ap + kk + aC,     aValid);
        cp16(&As[buf][aRow][aC + 4], Ap + kk + aC + 4, aValid);
        const float* bsrc = Bp + (size_t)(kk + bK) * ldb + bC;
        cp16(&Bs[buf][bK][bC],     bsrc,     true);
        cp16(&Bs[buf][bK][bC + 4], bsrc + 4, true);
    };

    float d[4][4][4];
#pragma unroll
    for (int i = 0; i < 4; i++)
#pragma unroll
        for (int j = 0; j < 4; j++)
#pragma unroll
            for (int q = 0; q < 4; q++) d[i][j][q] = 0.f;

    const int NIT = KTOT / BK;
    load_tiles(0, 0);
    CP_COMMIT();

    for (int it = 0; it < NIT; it++) {
        const int buf = it & 1;
        if (it + 1 < NIT) {
            load_tiles(buf ^ 1, (it + 1) * BK);
            CP_COMMIT();
            CP_WAIT(1);
        } else {
            CP_WAIT(0);
        }
        __syncthreads();

#pragma unroll
        for (int kb = 0; kb < BK; kb += 8) {
            uint32_t ahi[4][4], alo[4][4];
            uint32_t bhi[4][2], blo[4][2];
#pragma unroll
            for (int mt = 0; mt < 4; mt++) {
                int r = wm * 64 + mt * 16 + (lane >> 2);
                int c = kb + (lane & 3);
                split_tf32(As[buf][r][c],         ahi[mt][0], alo[mt][0]);
                split_tf32(As[buf][r + 8][c],     ahi[mt][1], alo[mt][1]);
                split_tf32(As[buf][r][c + 4],     ahi[mt][2], alo[mt][2]);
                split_tf32(As[buf][r + 8][c + 4], ahi[mt][3], alo[mt][3]);
            }
#pragma unroll
            for (int nt = 0; nt < 4; nt++) {
                int n = wn * 32 + nt * 8 + (lane >> 2);
                int k = kb + (lane & 3);
                split_tf32(Bs[buf][k][n],     bhi[nt][0], blo[nt][0]);
                split_tf32(Bs[buf][k + 4][n], bhi[nt][1], blo[nt][1]);
            }
            // split-major ordering: 16 independent accumulators between reuses
#pragma unroll
            for (int mt = 0; mt < 4; mt++)
#pragma unroll
                for (int nt = 0; nt < 4; nt++) MMA_TF32(d[mt][nt], ahi[mt], bhi[nt]);
#pragma unroll
            for (int mt = 0; mt < 4; mt++)
#pragma unroll
                for (int nt = 0; nt < 4; nt++) MMA_TF32(d[mt][nt], ahi[mt], blo[nt]);
#pragma unroll
            for (int mt = 0; mt < 4; mt++)
#pragma unroll
                for (int nt = 0; nt < 4; nt++) MMA_TF32(d[mt][nt], alo[mt], bhi[nt]);
        }
        __syncthreads();
    }

    // ---- epilogue: bias (+relu), write ----
    float bb0[4], bb1[4];
#pragma unroll
    for (int nt = 0; nt < 4; nt++) {
        int cb = wn * 32 + nt * 8 + 2 * (lane & 3);
        bb0[nt] = bias[bias_off + cb];
        bb1[nt] = bias[bias_off + cb + 1];
    }

#pragma unroll
    for (int mt = 0; mt < 4; mt++) {
#pragma unroll
        for (int half = 0; half < 2; half++) {
            int p = m0 + wm * 64 + mt * 16 + (lane >> 2) + half * 8;
            if ((MODE == 2 || MODE == 3) && p >= mend) continue;
            float* dstrow;
            if (MODE == 0)      dstrow = g_h1s  + (size_t)p * (SS * HH) + colstart;
            else if (MODE == 1) dstrow = g_outs + (size_t)p * (SS * DD) + colstart;
            else if (MODE == 2) dstrow = g_h1g  + (size_t)p * (GG * HH) + colstart;
            else {
                int tok = g_perm[p];
                dstrow = g_outg + (size_t)tok * (GG * DD) + colstart;
            }
#pragma unroll
            for (int nt = 0; nt < 4; nt++) {
                int cb = wn * 32 + nt * 8 + 2 * (lane & 3);
                float v0 = d[mt][nt][half * 2 + 0] + bb0[nt];
                float v1 = d[mt][nt][half * 2 + 1] + bb1[nt];
                if (MODE == 0 || MODE == 2) {
                    v0 = v0 > 0.f ? v0 : 0.f;
                    v1 = v1 > 0.f ? v1 : 0.f;
                }
                *reinterpret_cast<float2*>(dstrow + cb) = make_float2(v0, v1);
            }
        }
    }
}

// ---------------- gate + combine -------------------------------------------
__global__ void k_gate(const float* __restrict__ x,
                       const float* __restrict__ cond_emb,
                       const float* __restrict__ gate_W,
                       const float* __restrict__ gate_b,
                       float* __restrict__ out) {
    const int n = blockIdx.x;
    const int FD = DD + CC;       // 544
    __shared__ float gx[DD + CC];
    __shared__ float lg[KK * 4];
    __shared__ float w[KK * 4];
    const int t = threadIdx.x;    // 128 threads
    const float* xr = x + (size_t)n * DD;
    for (int i = t; i < DD; i += 128) gx[i] = xr[i];
    int gid = g_gid[n];
    if (t < CC) gx[DD + t] = cond_emb[gid * CC + t];
    __syncthreads();

    const int warp = t >> 5, lane = t & 31;
    const int p0 = warp * 3;      // 12 (k,e) pairs total
    float part0 = 0.f, part1 = 0.f, part2 = 0.f;
    for (int f = lane; f < FD; f += 32) {
        float xv = gx[f];
        int p;
        p = p0 + 0; part0 = fmaf(xv, gate_W[((p >> 2) * FD + f) * 4 + (p & 3)], part0);
        p = p0 + 1; part1 = fmaf(xv, gate_W[((p >> 2) * FD + f) * 4 + (p & 3)], part1);
        p = p0 + 2; part2 = fmaf(xv, gate_W[((p >> 2) * FD + f) * 4 + (p & 3)], part2);
    }
#pragma unroll
    for (int off = 16; off > 0; off >>= 1) {
        part0 += __shfl_down_sync(0xffffffffu, part0, off);
        part1 += __shfl_down_sync(0xffffffffu, part1, off);
        part2 += __shfl_down_sync(0xffffffffu, part2, off);
    }
    if (lane == 0) {
        lg[p0 + 0] = part0 + gate_b[p0 + 0];
        lg[p0 + 1] = part1 + gate_b[p0 + 1];
        lg[p0 + 2] = part2 + gate_b[p0 + 2];
    }
    __syncthreads();
    if (t < KK) {
        float l0 = lg[t * 4 + 0], l1 = lg[t * 4 + 1], l2 = lg[t * 4 + 2], l3 = lg[t * 4 + 3];
        float m = fmaxf(fmaxf(l0, l1), fmaxf(l2, l3));
        float e0 = expf(l0 - m), e1 = expf(l1 - m), e2 = expf(l2 - m), e3 = expf(l3 - m);
        float inv = 1.f / (e0 + e1 + e2 + e3);
        w[t * 4 + 0] = e0 * inv; w[t * 4 + 1] = e1 * inv;
        w[t * 4 + 2] = e2 * inv; w[t * 4 + 3] = e3 * inv;
    }
    __syncthreads();

    const float* so = g_outs + (size_t)n * (SS * DD);
    const float* go = g_outg + (size_t)n * (GG * DD);
    for (int d = t; d < DD; d += 128) {
        float e0 = so[d], e1 = so[DD + d], e2 = go[d], e3 = go[DD + d];
#pragma unroll
        for (int k = 0; k < KK; k++) {
            float r = w[k * 4 + 0] * e0 + w[k * 4 + 1] * e1
                    + w[k * 4 + 2] * e2 + w[k * 4 + 3] * e3;
            out[((size_t)k * NTOK + n) * DD + d] = r;
        }
    }
}

// ---------------- launch -----------------------------------------------------
extern "C" void kernel_launch(void* const* d_in, const int* in_sizes, int n_in,
                              void* d_out, int out_size) {
    const float* x    = (const float*)d_in[0];
    const int*   nti  = (const int*)d_in[1];
    const int*   e2g  = (const int*)d_in[2];
    const float* Ws1  = (const float*)d_in[3];
    const float* bs1  = (const float*)d_in[4];
    const float* Ws2  = (const float*)d_in[5];
    const float* bs2  = (const float*)d_in[6];
    const float* Wg1  = (const float*)d_in[7];
    const float* bg1  = (const float*)d_in[8];
    const float* Wg2  = (const float*)d_in[9];
    const float* bg2  = (const float*)d_in[10];
    const float* cemb = (const float*)d_in[11];
    const float* gW   = (const float*)d_in[12];
    const float* gb   = (const float*)d_in[13];
    float* out = (float*)d_out;

    k_prep<<<1, 256>>>(nti, e2g);
    dim3 blk(256);
    // layer 1 (shared + grouped)
    k_mma<0><<<dim3(NTOK / BM, (SS * HH) / BN), blk>>>(x, Ws1, bs1);
    k_mma<2><<<dim3(MAXTILES, (GG * HH) / BN), blk>>>(x, Wg1, bg1);
    // layer 2
    k_mma<1><<<dim3(NTOK / BM, (SS * DD) / BN), blk>>>(nullptr, Ws2, bs2);
    k_mma<3><<<dim3(MAXTILES, (GG * DD) / BN), blk>>>(nullptr, Wg2, bg2);
    // gates + mixture
    k_gate<<<NTOK, 128>>>(x, cemb, gW, gb, out);
}

// round 9
// speedup vs baseline: 1.3997x; 1.3997x over previous
#include <cuda_runtime.h>
#include <cuda_fp16.h>
#include <stdint.h>

#define DD 512
#define HH 1024
#define NTOK 4096
#define SS 2
#define GG 2
#define NGR 6
#define CC 32
#define KK 3
#define NEVT 50
#define BM 128
#define BN 128
#define BK 32
#define MAXTILES 40
#define NBANK (SS + NGR * GG)
#define LDHB 80            // bytes per smem row (32 halfs + 8 pad)
#define ABUF 10240         // bytes per buffer per array (128*80)
#define OFF_AL 20480
#define OFF_BH 40960
#define OFF_BL 61440
#define SMEM_TOT 81920

// ---------------- device scratch (no cudaMalloc allowed) --------------------
__device__ __half gx_hi[NTOK * DD], gx_lo[NTOK * DD];
__device__ __half gw1_hi[NBANK * HH * DD], gw1_lo[NBANK * HH * DD];   // [bank][N][K]
__device__ __half gw2_hi[NBANK * DD * HH], gw2_lo[NBANK * DD * HH];
__device__ __half gh1s_hi[NTOK * SS * HH], gh1s_lo[NTOK * SS * HH];
__device__ __half gh1g_hi[NTOK * GG * HH], gh1g_lo[NTOK * GG * HH];
__device__ float g_outs[NTOK * SS * DD], g_outg[NTOK * GG * DD];
__device__ int g_gid[NTOK], g_perm[NTOK];
__device__ int g_tile_group[MAXTILES], g_tile_m0[MAXTILES], g_tile_end[MAXTILES], g_ntiles;

// ---------------- PTX helpers ------------------------------------------------
__device__ __forceinline__ void cp16(uint32_t d, const void* s, bool v) {
    int sz = v ? 16 : 0;
    asm volatile("cp.async.cg.shared.global [%0], [%1], 16, %2;" :: "r"(d), "l"(s), "r"(sz));
}
#define CPC() asm volatile("cp.async.commit_group;")
#define CPW(N) asm volatile("cp.async.wait_group %0;" :: "n"(N))
#define LDSM4(r, a) asm volatile("ldmatrix.sync.aligned.m8n8.x4.shared.b16 {%0,%1,%2,%3}, [%4];" \
    : "=r"((r)[0]), "=r"((r)[1]), "=r"((r)[2]), "=r"((r)[3]) : "r"(a))
#define MMA16(d, a, b) asm volatile( \
    "mma.sync.aligned.m16n8k16.row.col.f32.f16.f16.f32 " \
    "{%0,%1,%2,%3}, {%4,%5,%6,%7}, {%8,%9}, {%0,%1,%2,%3};" \
    : "+f"((d)[0]), "+f"((d)[1]), "+f"((d)[2]), "+f"((d)[3]) \
    : "r"((a)[0]), "r"((a)[1]), "r"((a)[2]), "r"((a)[3]), "r"((b)[0]), "r"((b)[1]))

// ---------------- prep: group ids + counting sort + tile table --------------
__global__ void k_prep(const int* __restrict__ nti, const int* __restrict__ e2g) {
    __shared__ int cnt[NGR], st[NGR], cur[NGR];
    int t = threadIdx.x;
    if (t < NGR) cnt[t] = 0;
    __syncthreads();
    for (int n = t; n < NTOK; n += blockDim.x) {
        int v = nti[n]; v = v < 0 ? 0 : (v > NEVT - 1 ? NEVT - 1 : v);
        int g = e2g[v]; g_gid[n] = g; atomicAdd(&cnt[g], 1);
    }
    __syncthreads();
    if (t == 0) {
        int acc = 0, ntl = 0;
        for (int g = 0; g < NGR; g++) {
            st[g] = acc; int c = cnt[g];
            for (int m0 = acc; m0 < acc + c; m0 += BM) {
                g_tile_group[ntl] = g; g_tile_m0[ntl] = m0; g_tile_end[ntl] = acc + c; ntl++;
            }
            acc += c;
        }
        g_ntiles = ntl;
        for (int g = 0; g < NGR; g++) cur[g] = st[g];
    }
    __syncthreads();
    for (int n = t; n < NTOK; n += blockDim.x) {
        int pos = atomicAdd(&cur[g_gid[n]], 1);
        g_perm[pos] = n;
    }
}

// ---------------- split x -> fp16 hi/lo --------------------------------------
__global__ void k_cvt_x(const float* __restrict__ x) {
    int i = blockIdx.x * 256 + threadIdx.x;
    float v = x[i];
    __half h = __float2half_rn(v);
    gx_hi[i] = h;
    gx_lo[i] = __float2half_rn(v - __half2float(h));
}

// src [nb][Kd][Nd] fp32 -> dst [bank0+b][Nd][Kd] fp16 hi/lo (transposed)
__global__ void k_cvt_w(const float* __restrict__ src, int Kd, int Nd, int which, int bank0) {
    __shared__ float t[32][33];
    int b = blockIdx.z, k0 = blockIdx.x * 32, n0 = blockIdx.y * 32;
    const float* s = src + (size_t)b * Kd * Nd;
    for (int r = threadIdx.y; r < 32; r += 8)
        t[r][threadIdx.x] = s[(size_t)(k0 + r) * Nd + n0 + threadIdx.x];
    __syncthreads();
    __half* dh = which ? gw2_hi : gw1_hi;
    __half* dl = which ? gw2_lo : gw1_lo;
    for (int r = threadIdx.y; r < 32; r += 8) {
        float v = t[threadIdx.x][r];
        __half h = __float2half_rn(v);
        size_t o = ((size_t)(bank0 + b) * Nd + n0 + r) * Kd + k0 + threadIdx.x;
        dh[o] = h;
        dl[o] = __float2half_rn(v - __half2float(h));
    }
}

// ---------------- fp16x3 tensor GEMM -----------------------------------------
// MODE 0: h1s=relu(x@Ws1+bs1)  1: outs=h1s@Ws2+bs2  2: grouped L1  3: grouped L2
// D += Ah*Bh + Ah*Bl + Al*Bh   (fp32 accum; lo*lo term ~2^-24, dropped)
template <int MODE>
__global__ void __launch_bounds__(256)
k_mma(const float* __restrict__ bias) {
    int m0, mend, g = 0;
    if (MODE >= 2) {
        int tile = blockIdx.x;
        if (tile >= g_ntiles) return;
        g = g_tile_group[tile]; m0 = g_tile_m0[tile]; mend = g_tile_end[tile];
    } else { m0 = blockIdx.x * BM; mend = NTOK; }
    const int colstart = blockIdx.y * BN;
    const int KTOT = (MODE == 0 || MODE == 2) ? DD : HH;

    extern __shared__ char dsm[];
    const uint32_t base = (uint32_t)__cvta_generic_to_shared(dsm);

    const int tid = threadIdx.x;
    const int lane = tid & 31;
    const int warp = tid >> 5;
    const int wm = warp >> 2;     // 0..1 -> 64 rows
    const int wn = warp & 3;      // 0..3 -> 32 cols

    // ---- B bank row pointers (loader rows r0, r1) ----
    int bias_off, seg;
    const __half *wH, *wL;
    if (MODE == 0 || MODE == 2) {
        seg = colstart >> 10;
        int bank = (MODE == 0) ? seg : (SS + g * GG + seg);
        size_t bo = ((size_t)bank * HH + (colstart & (HH - 1)));
        wH = gw1_hi + bo * DD; wL = gw1_lo + bo * DD;
        bias_off = (MODE == 0) ? colstart : g * (GG * HH) + colstart;
    } else {
        seg = colstart >> 9;
        int bank = (MODE == 1) ? seg : (SS + g * GG + seg);
        size_t bo = ((size_t)bank * DD + (colstart & (DD - 1)));
        wH = gw2_hi + bo * HH; wL = gw2_lo + bo * HH;
        bias_off = (MODE == 1) ? colstart : g * (GG * DD) + colstart;
    }

    // ---- loader mapping: thread handles chunks tid and tid+256 ----
    const int r0 = tid >> 2, r1 = 64 + (tid >> 2);
    const uint32_t cb = (uint32_t)(tid & 3) * 16;
    const uint32_t o0 = (uint32_t)r0 * LDHB + cb, o1 = (uint32_t)r1 * LDHB + cb;
    const int kadd = (tid & 3) * 8;

    const __half *pa0h, *pa0l, *pa1h, *pa1l;
    bool v0 = true, v1 = true;
    {
        int p0 = m0 + r0, p1 = m0 + r1;
        if (MODE == 0) {
            pa0h = gx_hi + (size_t)p0 * DD; pa0l = gx_lo + (size_t)p0 * DD;
            pa1h = gx_hi + (size_t)p1 * DD; pa1l = gx_lo + (size_t)p1 * DD;
        } else if (MODE == 1) {
            size_t q0 = (size_t)p0 * (SS * HH) + seg * HH, q1 = (size_t)p1 * (SS * HH) + seg * HH;
            pa0h = gh1s_hi + q0; pa0l = gh1s_lo + q0;
            pa1h = gh1s_hi + q1; pa1l = gh1s_lo + q1;
        } else if (MODE == 2) {
            v0 = p0 < mend; v1 = p1 < mend;
            int t0 = v0 ? g_perm[p0] : 0, t1 = v1 ? g_perm[p1] : 0;
            pa0h = gx_hi + (size_t)t0 * DD; pa0l = gx_lo + (size_t)t0 * DD;
            pa1h = gx_hi + (size_t)t1 * DD; pa1l = gx_lo + (size_t)t1 * DD;
        } else {
            v0 = p0 < mend; v1 = p1 < mend;
            size_t q0 = (size_t)(v0 ? p0 : 0) * (GG * HH) + seg * HH;
            size_t q1 = (size_t)(v1 ? p1 : 0) * (GG * HH) + seg * HH;
            pa0h = gh1g_hi + q0; pa0l = gh1g_lo + q0;
            pa1h = gh1g_hi + q1; pa1l = gh1g_lo + q1;
        }
    }
    const __half* pb0h = wH + (size_t)r0 * KTOT;
    const __half* pb1h = wH + (size_t)r1 * KTOT;
    const __half* pb0l = wL + (size_t)r0 * KTOT;
    const __half* pb1l = wL + (size_t)r1 * KTOT;

    auto load = [&](int buf, int kk) {
        uint32_t aB = base + buf * ABUF;
        int ke = kk + kadd;
        cp16(aB + o0, pa0h + ke, v0);
        cp16(aB + o1, pa1h + ke, v1);
        cp16(aB + OFF_AL + o0, pa0l + ke, v0);
        cp16(aB + OFF_AL + o1, pa1l + ke, v1);
        cp16(aB + OFF_BH + o0, pb0h + ke, true);
        cp16(aB + OFF_BH + o1, pb1h + ke, true);
        cp16(aB + OFF_BL + o0, pb0l + ke, true);
        cp16(aB + OFF_BL + o1, pb1l + ke, true);
        CPC();
    };

    float d[4][4][4];
#pragma unroll
    for (int i = 0; i < 4; i++)
#pragma unroll
        for (int j = 0; j < 4; j++)
#pragma unroll
            for (int q = 0; q < 4; q++) d[i][j][q] = 0.f;

    const int NIT = KTOT / BK;
    load(0, 0);

    for (int it = 0; it < NIT; it++) {
        const int buf = it & 1;
        if (it + 1 < NIT) { load(buf ^ 1, (it + 1) * BK); CPW(1); }
        else CPW(0);
        __syncthreads();

#pragma unroll
        for (int ks = 0; ks < 2; ks++) {
            const uint32_t colb = (uint32_t)((ks * 16 + ((lane >> 4) << 3)) << 1);
            uint32_t ah[4][4], al[4][4], bh[4][2], bl[4][2];
#pragma unroll
            for (int mt = 0; mt < 4; mt++) {
                uint32_t addr = base + buf * ABUF
                              + (uint32_t)(wm * 64 + mt * 16 + (lane & 15)) * LDHB + colb;
                LDSM4(ah[mt], addr);
                LDSM4(al[mt], addr + OFF_AL);
            }
#pragma unroll
            for (int np = 0; np < 2; np++) {
                uint32_t addr = base + buf * ABUF + OFF_BH
                              + (uint32_t)(wn * 32 + np * 16 + (lane & 15)) * LDHB + colb;
                uint32_t q[4];
                LDSM4(q, addr);
                bh[np * 2][0] = q[0]; bh[np * 2][1] = q[2];
                bh[np * 2 + 1][0] = q[1]; bh[np * 2 + 1][1] = q[3];
                LDSM4(q, addr + 20480);          // OFF_BL - OFF_BH
                bl[np * 2][0] = q[0]; bl[np * 2][1] = q[2];
                bl[np * 2 + 1][0] = q[1]; bl[np * 2 + 1][1] = q[3];
            }
#pragma unroll
            for (int mt = 0; mt < 4; mt++)
#pragma unroll
                for (int nt = 0; nt < 4; nt++) MMA16(d[mt][nt], ah[mt], bh[nt]);
#pragma unroll
            for (int mt = 0; mt < 4; mt++)
#pragma unroll
                for (int nt = 0; nt < 4; nt++) MMA16(d[mt][nt], ah[mt], bl[nt]);
#pragma unroll
            for (int mt = 0; mt < 4; mt++)
#pragma unroll
                for (int nt = 0; nt < 4; nt++) MMA16(d[mt][nt], al[mt], bh[nt]);
        }
        __syncthreads();
    }

    // ---- epilogue: bias (+relu/split or fp32 store) ----
    float bb0[4], bb1[4];
#pragma unroll
    for (int nt = 0; nt < 4; nt++) {
        int cbx = wn * 32 + nt * 8 + 2 * (lane & 3);
        bb0[nt] = bias[bias_off + cbx];
        bb1[nt] = bias[bias_off + cbx + 1];
    }

#pragma unroll
    for (int mt = 0; mt < 4; mt++) {
#pragma unroll
        for (int half = 0; half < 2; half++) {
            int p = m0 + wm * 64 + mt * 16 + (lane >> 2) + half * 8;
            if ((MODE >= 2) && p >= mend) continue;
            if (MODE == 0 || MODE == 2) {
                __half *dh, *dl;
                if (MODE == 0) {
                    size_t o = (size_t)p * (SS * HH) + colstart;
                    dh = gh1s_hi + o; dl = gh1s_lo + o;
                } else {
                    size_t o = (size_t)p * (GG * HH) + colstart;
                    dh = gh1g_hi + o; dl = gh1g_lo + o;
                }
#pragma unroll
                for (int nt = 0; nt < 4; nt++) {
                    int cbx = wn * 32 + nt * 8 + 2 * (lane & 3);
                    float u0 = d[mt][nt][half * 2 + 0] + bb0[nt];
                    float u1 = d[mt][nt][half * 2 + 1] + bb1[nt];
                    u0 = u0 > 0.f ? u0 : 0.f;
                    u1 = u1 > 0.f ? u1 : 0.f;
                    __half h0 = __float2half_rn(u0), h1 = __float2half_rn(u1);
                    __half2 H; H.x = h0; H.y = h1;
                    __half2 L;
                    L.x = __float2half_rn(u0 - __half2float(h0));
                    L.y = __float2half_rn(u1 - __half2float(h1));
                    *reinterpret_cast<__half2*>(dh + cbx) = H;
                    *reinterpret_cast<__half2*>(dl + cbx) = L;
                }
            } else {
                float* dst = (MODE == 1) ? g_outs + (size_t)p * (SS * DD) + colstart
                                         : g_outg + (size_t)g_perm[p] * (GG * DD) + colstart;
#pragma unroll
                for (int nt = 0; nt < 4; nt++) {
                    int cbx = wn * 32 + nt * 8 + 2 * (lane & 3);
                    float u0 = d[mt][nt][half * 2 + 0] + bb0[nt];
                    float u1 = d[mt][nt][half * 2 + 1] + bb1[nt];
                    *reinterpret_cast<float2*>(dst + cbx) = make_float2(u0, u1);
                }
            }
        }
    }
}

// ---------------- gate + combine ---------------------------------------------
__global__ void k_gate(const float* __restrict__ x, const float* __restrict__ cond_emb,
                       const float* __restrict__ gate_W, const float* __restrict__ gate_b,
                       float* __restrict__ out) {
    const int n = blockIdx.x;
    const int FD = DD + CC;
    __shared__ float gx[DD + CC], lg[KK * 4], w[KK * 4];
    const int t = threadIdx.x;
    const float* xr = x + (size_t)n * DD;
    for (int i = t; i < DD; i += 128) gx[i] = xr[i];
    if (t < CC) gx[DD + t] = cond_emb[g_gid[n] * CC + t];
    __syncthreads();
    const int warp = t >> 5, lane = t & 31, p0 = warp * 3;
    float s0 = 0.f, s1 = 0.f, s2 = 0.f;
    for (int f = lane; f < FD; f += 32) {
        float xv = gx[f];
        int p;
        p = p0 + 0; s0 = fmaf(xv, gate_W[((p >> 2) * FD + f) * 4 + (p & 3)], s0);
        p = p0 + 1; s1 = fmaf(xv, gate_W[((p >> 2) * FD + f) * 4 + (p & 3)], s1);
        p = p0 + 2; s2 = fmaf(xv, gate_W[((p >> 2) * FD + f) * 4 + (p & 3)], s2);
    }
#pragma unroll
    for (int o = 16; o > 0; o >>= 1) {
        s0 += __shfl_down_sync(0xffffffffu, s0, o);
        s1 += __shfl_down_sync(0xffffffffu, s1, o);
        s2 += __shfl_down_sync(0xffffffffu, s2, o);
    }
    if (lane == 0) {
        lg[p0 + 0] = s0 + gate_b[p0 + 0];
        lg[p0 + 1] = s1 + gate_b[p0 + 1];
        lg[p0 + 2] = s2 + gate_b[p0 + 2];
    }
    __syncthreads();
    if (t < KK) {
        float l0 = lg[t * 4], l1 = lg[t * 4 + 1], l2 = lg[t * 4 + 2], l3 = lg[t * 4 + 3];
        float m = fmaxf(fmaxf(l0, l1), fmaxf(l2, l3));
        float e0 = expf(l0 - m), e1 = expf(l1 - m), e2 = expf(l2 - m), e3 = expf(l3 - m);
        float inv = 1.f / (e0 + e1 + e2 + e3);
        w[t * 4] = e0 * inv; w[t * 4 + 1] = e1 * inv;
        w[t * 4 + 2] = e2 * inv; w[t * 4 + 3] = e3 * inv;
    }
    __syncthreads();
    const float* so = g_outs + (size_t)n * (SS * DD);
    const float* go = g_outg + (size_t)n * (GG * DD);
    for (int d = t; d < DD; d += 128) {
        float e0 = so[d], e1 = so[DD + d], e2 = go[d], e3 = go[DD + d];
#pragma unroll
        for (int k = 0; k < KK; k++)
            out[((size_t)k * NTOK + n) * DD + d] =
                w[k * 4] * e0 + w[k * 4 + 1] * e1 + w[k * 4 + 2] * e2 + w[k * 4 + 3] * e3;
    }
}

// ---------------- launch ------------------------------------------------------
extern "C" void kernel_launch(void* const* d_in, const int* in_sizes, int n_in,
                              void* d_out, int out_size) {
    const float* x   = (const float*)d_in[0];
    const int* nti   = (const int*)d_in[1];
    const int* e2g   = (const int*)d_in[2];
    const float* Ws1 = (const float*)d_in[3];
    const float* bs1 = (const float*)d_in[4];
    const float* Ws2 = (const float*)d_in[5];
    const float* bs2 = (const float*)d_in[6];
    const float* Wg1 = (const float*)d_in[7];
    const float* bg1 = (const float*)d_in[8];
    const float* Wg2 = (const float*)d_in[9];
    const float* bg2 = (const float*)d_in[10];
    const float* cemb = (const float*)d_in[11];
    const float* gW  = (const float*)d_in[12];
    const float* gb  = (const float*)d_in[13];
    float* out = (float*)d_out;

    cudaFuncSetAttribute(k_mma<0>, cudaFuncAttributeMaxDynamicSharedMemorySize, SMEM_TOT);
    cudaFuncSetAttribute(k_mma<1>, cudaFuncAttributeMaxDynamicSharedMemorySize, SMEM_TOT);
    cudaFuncSetAttribute(k_mma<2>, cudaFuncAttributeMaxDynamicSharedMemorySize, SMEM_TOT);
    cudaFuncSetAttribute(k_mma<3>, cudaFuncAttributeMaxDynamicSharedMemorySize, SMEM_TOT);

    k_prep<<<1, 256>>>(nti, e2g);
    k_cvt_x<<<NTOK * DD / 256, 256>>>(x);
    k_cvt_w<<<dim3(DD / 32, HH / 32, SS), dim3(32, 8)>>>(Ws1, DD, HH, 0, 0);
    k_cvt_w<<<dim3(DD / 32, HH / 32, NGR * GG), dim3(32, 8)>>>(Wg1, DD, HH, 0, SS);
    k_cvt_w<<<dim3(HH / 32, DD / 32, SS), dim3(32, 8)>>>(Ws2, HH, DD, 1, 0);
    k_cvt_w<<<dim3(HH / 32, DD / 32, NGR * GG), dim3(32, 8)>>>(Wg2, HH, DD, 1, SS);
    k_mma<0><<<dim3(NTOK / BM, (SS * HH) / BN), 256, SMEM_TOT>>>(bs1);
    k_mma<2><<<dim3(MAXTILES, (GG * HH) / BN), 256, SMEM_TOT>>>(bg1);
    k_mma<1><<<dim3(NTOK / BM, (SS * DD) / BN), 256, SMEM_TOT>>>(bs2);
    k_mma<3><<<dim3(MAXTILES, (GG * DD) / BN), 256, SMEM_TOT>>>(bg2);
    k_gate<<<NTOK, 128>>>(x, cemb, gW, gb, out);
}